// round 6
// baseline (speedup 1.0000x reference)
#include <cuda_runtime.h>
#include <cstdint>

#define FULLMASK 0xffffffffu
#define R_TOT 65536

// ---------------- device scratch (no allocs allowed) ----------------
__device__ float g_scores[(size_t)R_TOT * 2048];          // 512MB
// q_norm, transposed per 128-row block: [b][half][k 0..127][row&127]
__device__ __align__(16) float g_qnT[(size_t)R_TOT * 256];   // 64MB
// keys, duplicated pairs, chunked: 32 chunks x 16384 floats
//   chunk ci = (half*8+nb)*2+kc ; within: [k' 0..63][j 0..3][tx 0..15][4]
//   the 4 floats are [v(c), v(c), v(c+1), v(c+1)], c = nb*128 + tx*8 + j*2
__device__ __align__(16) float g_ktp[32 * 16384];            // 2MB

// Joint candidates: (i+1)*(j+1) <= 16 (dominance argument) -> 50 cells
__constant__ unsigned char c_CI[50] = {
    0,0,0,0,0,0,0,0,0,0,0,0,0,0,0,0, 1,1,1,1,1,1,1,1, 2,2,2,2,2,
    3,3,3,3, 4,4,4, 5,5, 6,6, 7,7, 8,9,10,11,12,13,14,15
};
__constant__ unsigned char c_CJ[50] = {
    0,1,2,3,4,5,6,7,8,9,10,11,12,13,14,15, 0,1,2,3,4,5,6,7, 0,1,2,3,4,
    0,1,2,3, 0,1,2, 0,1, 0,1, 0,1, 0,0,0,0,0,0,0,0
};

__device__ __forceinline__ unsigned fmono(float f) {
    unsigned u = __float_as_uint(f);
    return u ^ (unsigned)(((int)u >> 31) | (int)0x80000000);
}
__device__ __forceinline__ float funmono(unsigned m) {
    return __uint_as_float((m & 0x80000000u) ? (m ^ 0x80000000u) : ~m);
}

// ---------------------------------------------------------------------------
// K1: LayerNorm — bit-exact Round-1/5 numerics; writes transposed q_norm.
// ---------------------------------------------------------------------------
__global__ __launch_bounds__(256)
void pkr_ln(const float* __restrict__ query,
            const float* __restrict__ gma,
            const float* __restrict__ bta)
{
    const int tid = threadIdx.x;
    const int r = tid >> 3, g = tid & 7;
    const int row = blockIdx.x * 32 + r;

    const float4* qp = (const float4*)(query + (size_t)row * 256);
    float4 v[8];
    float s = 0.f;
#pragma unroll
    for (int j = 0; j < 8; j++) {
        v[j] = qp[j * 8 + g];
        s += (v[j].x + v[j].y) + (v[j].z + v[j].w);
    }
#pragma unroll
    for (int off = 4; off >= 1; off >>= 1)
        s += __shfl_xor_sync(FULLMASK, s, off, 8);
    const float mu = s * (1.f / 256.f);

    float s2 = 0.f;
#pragma unroll
    for (int j = 0; j < 8; j++) {
        float dx = v[j].x - mu, dy = v[j].y - mu;
        float dz = v[j].z - mu, dw = v[j].w - mu;
        s2 += (dx * dx + dy * dy) + (dz * dz + dw * dw);
    }
#pragma unroll
    for (int off = 4; off >= 1; off >>= 1)
        s2 += __shfl_xor_sync(FULLMASK, s2, off, 8);

    const float varp = s2 * (1.f / 256.f) + 1e-5f;
    float rs = rsqrtf(varp);
    rs = rs * (1.5f - 0.5f * varp * rs * rs);

    const size_t bbase = (size_t)(row >> 7) * 32768;
    const int rl = row & 127;
#pragma unroll
    for (int j = 0; j < 8; j++) {
        const int c = j * 32 + g * 4;
        float d0 = (v[j].x - mu) * rs * gma[c + 0] + bta[c + 0];
        float d1 = (v[j].y - mu) * rs * gma[c + 1] + bta[c + 1];
        float d2 = (v[j].z - mu) * rs * gma[c + 2] + bta[c + 2];
        float d3 = (v[j].w - mu) * rs * gma[c + 3] + bta[c + 3];
        float dv[4] = {d0, d1, d2, d3};
#pragma unroll
        for (int i = 0; i < 4; i++) {
            const int ci = c + i;
            const int half = ci >> 7, kl = ci & 127;
            g_qnT[bbase + (size_t)half * 16384 + kl * 128 + rl] = dv[i];
        }
    }
}

// ---------------------------------------------------------------------------
// K2: keys pre-permute into duplicated-pair chunked layout (see g_ktp).
// ---------------------------------------------------------------------------
__global__ void pkr_kprep(const float* __restrict__ ck, const float* __restrict__ cp)
{
    const int o = blockIdx.x * 256 + threadIdx.x;   // 0..524287
    const int ci = o >> 14;
    const int rem = o & 16383;
    const int kq = rem >> 8;          // k' 0..63
    const int f  = rem & 255;
    const int j  = f >> 6, tx = (f >> 2) & 15, e = f & 3;
    const int half = ci >> 4;
    const int nb = (ci >> 1) & 7, kc = ci & 1;
    const int k = kc * 64 + kq;
    const int col = nb * 128 + tx * 8 + j * 2 + (e >> 1);
    const float* src = half ? cp : ck;
    g_ktp[o] = src[(size_t)col * 128 + k];
}

// ---------------------------------------------------------------------------
// K3: fp32x2 GEMM, cp.async double-buffered. BM=128, BN=128, 256 threads,
// 8 rows x 8 cols / thread (row-paired FMA2, zero PACK). Sequential-k accum
// per output (bit-exact vs Round 5 / reference ordering).
// ---------------------------------------------------------------------------
#define FMA2(d, a, b) \
    asm("fma.rn.f32x2 %0, %1, %2, %0;" : "+l"(d) : "l"(a), "l"(b))
#define CPA16(dst, src) \
    asm volatile("cp.async.cg.shared.global [%0], [%1], 16;" :: "r"(dst), "l"(src))
#define CPCOMMIT() asm volatile("cp.async.commit_group;")
#define CPWAIT(N)  asm volatile("cp.async.wait_group %0;" :: "n"(N))

__global__ __launch_bounds__(256, 1)
void pkr_gemm(void)
{
    extern __shared__ float smem[];
    float* qs = smem;                         // [128 k][128 rows] 64KB
    // kd buffers at +16384, +32768 floats (64KB each)

    const int tid = threadIdx.x;
    const int ty = tid >> 4;     // rows ty*8..+7
    const int tx = tid & 15;     // cols tx*8..+7
    const unsigned smem_s = (unsigned)__cvta_generic_to_shared(smem);
    const int rowBase = blockIdx.x * 128;

    unsigned long long acc[4][8];

#pragma unroll 1
    for (int i = 0; i < 32; ++i) {
        const int half = i >> 4;
        const int nb = (i >> 1) & 7;
        const int kc = i & 1;

        if ((i & 15) == 0) {
            // stage q for this half
            const float* qsrc = g_qnT + ((size_t)blockIdx.x * 2 + half) * 16384;
#pragma unroll
            for (int n = 0; n < 16; n++) {
                const int fidx = n * 256 + tid;    // float4 index
                CPA16(smem_s + fidx * 16, (const void*)(qsrc + fidx * 4));
            }
            CPCOMMIT();
            // stage chunk i
            const float* ksrc = g_ktp + (size_t)i * 16384;
            const unsigned kdst = smem_s + 65536 + (i & 1) * 65536;
#pragma unroll
            for (int n = 0; n < 16; n++) {
                const int fidx = n * 256 + tid;
                CPA16(kdst + fidx * 16, (const void*)(ksrc + fidx * 4));
            }
            CPCOMMIT();
        }
        const bool pre = ((i + 1) & 15) != 0;   // i+1<32 and not a half start
        if (pre) {
            const float* ksrc = g_ktp + (size_t)(i + 1) * 16384;
            const unsigned kdst = smem_s + 65536 + ((i + 1) & 1) * 65536;
#pragma unroll
            for (int n = 0; n < 16; n++) {
                const int fidx = n * 256 + tid;
                CPA16(kdst + fidx * 16, (const void*)(ksrc + fidx * 4));
            }
            CPCOMMIT();
            CPWAIT(1);
        } else {
            CPWAIT(0);
        }
        __syncthreads();

        if (kc == 0) {
#pragma unroll
            for (int p = 0; p < 4; p++)
#pragma unroll
                for (int c = 0; c < 8; c++) acc[p][c] = 0ull;
        }

        const float* qp0 = qs + kc * 8192 + ty * 8;
        const float* kp0 = smem + 16384 + (i & 1) * 16384 + tx * 4;

#pragma unroll 2
        for (int kq = 0; kq < 64; kq++) {
            uint4 qA = *(const uint4*)(qp0 + kq * 128);
            uint4 qB = *(const uint4*)(qp0 + kq * 128 + 4);
            unsigned long long qd[4];
            qd[0] = *(unsigned long long*)&qA.x;
            qd[1] = *(unsigned long long*)&qA.z;
            qd[2] = *(unsigned long long*)&qB.x;
            qd[3] = *(unsigned long long*)&qB.z;
#pragma unroll
            for (int j = 0; j < 4; j++) {
                uint4 kv = *(const uint4*)(kp0 + kq * 256 + j * 64);
                unsigned long long k0 = *(unsigned long long*)&kv.x;
                unsigned long long k1 = *(unsigned long long*)&kv.z;
#pragma unroll
                for (int p = 0; p < 4; p++) {
                    FMA2(acc[p][2 * j],     qd[p], k0);
                    FMA2(acc[p][2 * j + 1], qd[p], k1);
                }
            }
        }
        __syncthreads();

        if (kc == 1) {
            const int col0 = half * 1024 + nb * 128 + tx * 8;
#pragma unroll
            for (int p = 0; p < 4; p++) {
                float2 f[8];
#pragma unroll
                for (int c = 0; c < 8; c++) f[c] = *(float2*)&acc[p][c];
                float* pe = g_scores + (size_t)(rowBase + ty * 8 + 2 * p) * 2048 + col0;
                float* po = pe + 2048;
                *(float4*)(pe)     = make_float4(f[0].x, f[1].x, f[2].x, f[3].x);
                *(float4*)(pe + 4) = make_float4(f[4].x, f[5].x, f[6].x, f[7].x);
                *(float4*)(po)     = make_float4(f[0].y, f[1].y, f[2].y, f[3].y);
                *(float4*)(po + 4) = make_float4(f[4].y, f[5].y, f[6].y, f[7].y);
            }
        }
    }
}

// ---------------------------------------------------------------------------
// K4: selection v2 — scan-compaction + bitonic-64 sort fast path,
// ballot-insertion fallback. 2 warps/row, then 50-candidate joint top-16.
// ---------------------------------------------------------------------------
__global__ __launch_bounds__(256)
void pkr_select(float* __restrict__ out, int Rtot)
{
    __shared__ unsigned long long smQ[8][64];
    __shared__ unsigned long long smK[4][2][16];

    const int lane = threadIdx.x & 31;
    const int warp = threadIdx.x >> 5;
    const int r4   = warp >> 1;
    const int half = warp & 1;
    const int row  = blockIdx.x * 4 + r4;

    const float4* bp = (const float4*)(g_scores + (size_t)row * 2048 + half * 1024);
    float4 sv[8];
#pragma unroll
    for (int q2 = 0; q2 < 8; q2++) sv[q2] = bp[q2 * 32 + lane];

    float vmax = -3.4e38f;
#pragma unroll
    for (int q2 = 0; q2 < 8; q2++)
        vmax = fmaxf(vmax, fmaxf(fmaxf(sv[q2].x, sv[q2].y), fmaxf(sv[q2].z, sv[q2].w)));
    // T0 = min over 16 disjoint lane-pairs of pair-max (<= true rank-16 score)
    float pm = fmaxf(vmax, __shfl_xor_sync(FULLMASK, vmax, 1));
#pragma unroll
    for (int off = 2; off <= 16; off <<= 1)
        pm = fminf(pm, __shfl_xor_sync(FULLMASK, pm, off));
    const float T0f = pm;

    // candidate count + exclusive scan
    int cnt = 0;
#pragma unroll
    for (int q2 = 0; q2 < 8; q2++) {
        const float* vv = (const float*)&sv[q2];
#pragma unroll
        for (int t = 0; t < 4; t++) cnt += (vv[t] >= T0f);
    }
    int inc = cnt;
#pragma unroll
    for (int off = 1; off <= 16; off <<= 1) {
        int n = __shfl_up_sync(FULLMASK, inc, off);
        if (lane >= off) inc += n;
    }
    const int total = __shfl_sync(FULLMASK, inc, 31);
    int myoff = inc - cnt;

    unsigned long long rk = 0ull;
    const int lbase = 1023 - lane * 4;

    if (total <= 64) {
        smQ[warp][lane] = 0ull;
        smQ[warp][lane + 32] = 0ull;
        __syncwarp();
#pragma unroll
        for (int q2 = 0; q2 < 8; q2++) {
            const float* vv = (const float*)&sv[q2];
#pragma unroll
            for (int t = 0; t < 4; t++) {
                const float v = vv[t];
                if (v >= T0f) {
                    smQ[warp][myoff++] =
                        ((unsigned long long)fmono(v) << 32)
                        | (unsigned)(lbase - q2 * 128 - t);
                }
            }
        }
        __syncwarp();
        unsigned long long a = smQ[warp][lane];
        unsigned long long b = smQ[warp][lane + 32];
        // bitonic sort of 64 keys, descending (index = lane | lane+32)
#pragma unroll
        for (int k = 2; k <= 64; k <<= 1) {
#pragma unroll
            for (int j = 32; j >= 1; j >>= 1) {
                if (j >= k) continue;
                if (j == 32) {
                    unsigned long long mx = a > b ? a : b;
                    unsigned long long mn = a > b ? b : a;
                    a = mx; b = mn;
                } else {
                    const bool upa = ((lane & k) != 0);
                    const bool upb = (((lane + 32) & k) != 0);
                    const bool sel = ((lane & j) != 0);
                    unsigned long long oa = __shfl_xor_sync(FULLMASK, a, j);
                    unsigned long long ob = __shfl_xor_sync(FULLMASK, b, j);
                    a = (sel == upa) ? (a > oa ? a : oa) : (a < oa ? a : oa);
                    b = (sel == upb) ? (b > ob ? b : ob) : (b < ob ? b : ob);
                }
            }
        }
        rk = a;   // lane l holds rank-l key
    } else {
        // fallback: ballot insertion (identical to Round-5 path)
        float Tf = T0f;
#pragma unroll
        for (int q2 = 0; q2 < 8; q2++) {
            const float* vv = (const float*)&sv[q2];
#pragma unroll
            for (int t = 0; t < 4; t++) {
                const float v = vv[t];
                const bool p = (v >= Tf);
                unsigned long long K = ((unsigned long long)fmono(v) << 32)
                                     | (unsigned)(lbase - q2 * 128 - t);
                unsigned bal = __ballot_sync(FULLMASK, p);
                while (bal) {
                    const int src = __ffs(bal) - 1;
                    bal &= bal - 1;
                    const unsigned long long Kc = __shfl_sync(FULLMASK, K, src);
                    const unsigned mg = __ballot_sync(FULLMASK, (lane < 16) && (Kc > rk));
                    if (mg) {
                        const int pos = __ffs(mg) - 1;
                        const unsigned long long up = __shfl_up_sync(FULLMASK, rk, 1);
                        if (lane >= pos && lane < 16) rk = (lane == pos) ? Kc : up;
                    }
                    const unsigned long long T16 = __shfl_sync(FULLMASK, rk, 15);
                    Tf = fmaxf(T0f, funmono((unsigned)(T16 >> 32)));
                }
            }
        }
    }
    if (lane < 16) smK[r4][half][lane] = rk;
    __syncthreads();

    // ---- joint stage: warps 0..3 each handle one row ----
    if (warp < 4) {
        const int jr = warp;
        const unsigned long long k1 = smK[jr][0][lane & 15];
        const unsigned long long k2 = smK[jr][1][lane & 15];
        const float s1c = funmono((unsigned)(k1 >> 32));
        const float s2c = funmono((unsigned)(k2 >> 32));
        const int e1v = 1023 - (int)(unsigned)k1;
        const int e2v = 1023 - (int)(unsigned)k2;
        const int jrow = blockIdx.x * 4 + jr;

        const int i0 = c_CI[lane], j0 = c_CJ[lane];
        const int cid1 = lane + 32;
        const bool v1 = (cid1 < 50);
        const int i1 = c_CI[v1 ? cid1 : 0], j1 = c_CJ[v1 ? cid1 : 0];

        const float a0 = __shfl_sync(FULLMASK, s1c, i0);
        const float b0 = __shfl_sync(FULLMASK, s2c, j0);
        const float a1 = __shfl_sync(FULLMASK, s1c, i1);
        const float b1 = __shfl_sync(FULLMASK, s2c, j1);

        unsigned long long K0 =
            ((unsigned long long)fmono(a0 + b0) << 32) | (unsigned)(4095 - (i0 * 64 + j0));
        unsigned long long K1 = v1
            ? (((unsigned long long)fmono(a1 + b1) << 32) | (unsigned)(4095 - (i1 * 64 + j1)))
            : 0ull;

        unsigned long long last = ~0ull;
        unsigned long long resKey = 0ull;
#pragma unroll
        for (int r = 0; r < 16; r++) {
            unsigned long long m = (K0 < last) ? K0 : 0ull;
            if (K1 < last && K1 > m) m = K1;
#pragma unroll
            for (int off = 16; off >= 1; off >>= 1) {
                const unsigned long long o = __shfl_xor_sync(FULLMASK, m, off);
                if (o > m) m = o;
            }
            last = m;
            if (lane == r) resKey = m;
        }

        const int flat = 4095 - (int)((unsigned)resKey & 0xFFFu);
        const int ri = (flat >> 6) & 31;
        const int rj = flat & 31;
        const int er = __shfl_sync(FULLMASK, e1v, ri);
        const int ec = __shfl_sync(FULLMASK, e2v, rj);

        if (lane < 16) {
            out[(size_t)jrow * 16 + lane] = (float)(er * 1024 + ec);
            out[(size_t)Rtot * 16 + (size_t)jrow * 16 + lane] =
                funmono((unsigned)(resKey >> 32));
        }
    }
}

// ---------------------------------------------------------------------------
extern "C" void kernel_launch(void* const* d_in, const int* in_sizes, int n_in,
                              void* d_out, int out_size)
{
    const float* q   = (const float*)d_in[0];
    const float* ck  = (const float*)d_in[1];
    const float* cpk = (const float*)d_in[2];
    const float* gm  = (const float*)d_in[3];
    const float* bt  = (const float*)d_in[4];

    const int R = in_sizes[0] / 256;  // 65536

    cudaFuncSetAttribute(pkr_gemm, cudaFuncAttributeMaxDynamicSharedMemorySize, 196608);

    pkr_ln<<<R / 32, 256>>>(q, gm, bt);
    pkr_kprep<<<2048, 256>>>(ck, cpk);
    pkr_gemm<<<R / 128, 256, 196608>>>();
    pkr_select<<<R / 4, 256>>>((float*)d_out, R);
}

// round 8
// speedup vs baseline: 1.0705x; 1.0705x over previous
#include <cuda_runtime.h>
#include <cstdint>

#define FULLMASK 0xffffffffu
#define R_TOT 65536

// ---------------- device scratch (no allocs allowed) ----------------
__device__ float g_scores[(size_t)R_TOT * 2048];             // 512MB
// q_norm, transposed + DUPLICATED pairs: [b][half][k][2*rl {v,v}]
__device__ __align__(16) float g_qnT[(size_t)R_TOT * 512];   // 128MB
// keys, permuted (R5 layout), chunked by 32-k:
//  [half][nb 0..3][kc 0..3][kq 0..31][p 0..255], p=(cl*16+tx)*4+e,
//  col = nb*256 + (4*tx+cl)*4 + e, k = kc*32+kq
__device__ __align__(16) float g_ktp[262144];                // 1MB

// Joint candidates: (i+1)*(j+1) <= 16 (dominance argument) -> 50 cells
__constant__ unsigned char c_CI[50] = {
    0,0,0,0,0,0,0,0,0,0,0,0,0,0,0,0, 1,1,1,1,1,1,1,1, 2,2,2,2,2,
    3,3,3,3, 4,4,4, 5,5, 6,6, 7,7, 8,9,10,11,12,13,14,15
};
__constant__ unsigned char c_CJ[50] = {
    0,1,2,3,4,5,6,7,8,9,10,11,12,13,14,15, 0,1,2,3,4,5,6,7, 0,1,2,3,4,
    0,1,2,3, 0,1,2, 0,1, 0,1, 0,1, 0,0,0,0,0,0,0,0
};

__device__ __forceinline__ unsigned fmono(float f) {
    unsigned u = __float_as_uint(f);
    return u ^ (unsigned)(((int)u >> 31) | (int)0x80000000);
}
__device__ __forceinline__ float funmono(unsigned m) {
    return __uint_as_float((m & 0x80000000u) ? (m ^ 0x80000000u) : ~m);
}

// ---------------------------------------------------------------------------
// K1: LayerNorm — bit-exact Round-1/5 numerics; writes transposed q_norm
// with each value duplicated ({v,v} float2) for PACK-free FMA2 in the GEMM.
// ---------------------------------------------------------------------------
__global__ __launch_bounds__(256)
void pkr_ln(const float* __restrict__ query,
            const float* __restrict__ gma,
            const float* __restrict__ bta)
{
    const int tid = threadIdx.x;
    const int r = tid >> 3, g = tid & 7;
    const int row = blockIdx.x * 32 + r;

    const float4* qp = (const float4*)(query + (size_t)row * 256);
    float4 v[8];
    float s = 0.f;
#pragma unroll
    for (int j = 0; j < 8; j++) {
        v[j] = qp[j * 8 + g];
        s += (v[j].x + v[j].y) + (v[j].z + v[j].w);
    }
#pragma unroll
    for (int off = 4; off >= 1; off >>= 1)
        s += __shfl_xor_sync(FULLMASK, s, off, 8);
    const float mu = s * (1.f / 256.f);

    float s2 = 0.f;
#pragma unroll
    for (int j = 0; j < 8; j++) {
        float dx = v[j].x - mu, dy = v[j].y - mu;
        float dz = v[j].z - mu, dw = v[j].w - mu;
        s2 += (dx * dx + dy * dy) + (dz * dz + dw * dw);
    }
#pragma unroll
    for (int off = 4; off >= 1; off >>= 1)
        s2 += __shfl_xor_sync(FULLMASK, s2, off, 8);

    const float varp = s2 * (1.f / 256.f) + 1e-5f;
    float rs = rsqrtf(varp);
    rs = rs * (1.5f - 0.5f * varp * rs * rs);

    const size_t bbase = (size_t)(row >> 7) * 65536;   // 2 halves * 32768
    const int rl = row & 127;
#pragma unroll
    for (int j = 0; j < 8; j++) {
        const int c = j * 32 + g * 4;
        float d0 = (v[j].x - mu) * rs * gma[c + 0] + bta[c + 0];
        float d1 = (v[j].y - mu) * rs * gma[c + 1] + bta[c + 1];
        float d2 = (v[j].z - mu) * rs * gma[c + 2] + bta[c + 2];
        float d3 = (v[j].w - mu) * rs * gma[c + 3] + bta[c + 3];
        float dv[4] = {d0, d1, d2, d3};
#pragma unroll
        for (int i = 0; i < 4; i++) {
            const int ci = c + i;
            const int half = ci >> 7, kl = ci & 127;
            *(float2*)(g_qnT + bbase + (size_t)half * 32768
                       + kl * 256 + 2 * rl) = make_float2(dv[i], dv[i]);
        }
    }
}

// ---------------------------------------------------------------------------
// K2: keys pre-permute into chunked conflict-free layout (see g_ktp).
// ---------------------------------------------------------------------------
__global__ void pkr_kprep(const float* __restrict__ ck, const float* __restrict__ cp)
{
    const int o = blockIdx.x * 256 + threadIdx.x;   // 0..262143
    const int p  = o & 255;
    const int kq = (o >> 8) & 31;
    const int kc = (o >> 13) & 3;
    const int nb = (o >> 15) & 3;
    const int half = o >> 17;
    const int e = p & 3, s4 = p >> 2;
    const int tx = s4 & 15, cl = s4 >> 4;
    const int col = nb * 256 + (4 * tx + cl) * 4 + e;
    const int k = kc * 32 + kq;
    const float* src = half ? cp : ck;
    g_ktp[o] = src[(size_t)col * 128 + k];
}

// ---------------------------------------------------------------------------
// K3: fp32x2 GEMM, cp.async double-buffered, PACK-free (q duplicated).
// BM=128, BN=256, 256 threads, 8 rows x 16 cols / thread.
// Sequential-k accumulation per output (bit-exact vs Round 5 / reference).
// ---------------------------------------------------------------------------
#define FMA2(d, a, b) \
    asm("fma.rn.f32x2 %0, %1, %2, %0;" : "+l"(d) : "l"(a), "l"(b))
#define CPA16(dst, src) \
    asm volatile("cp.async.cg.shared.global [%0], [%1], 16;" :: "r"(dst), "l"(src))
#define CPCOMMIT() asm volatile("cp.async.commit_group;")
#define CPWAIT(N)  asm volatile("cp.async.wait_group %0;" :: "n"(N))

__device__ __forceinline__ void gemm_issue(int s, int blk, unsigned smem_s, int tid)
{
    const int half = s >> 4, nb = (s >> 2) & 3, kc = s & 3;
    const float* qsrc = g_qnT + ((size_t)blk * 2 + half) * 32768 + kc * 8192;
    const float* ksrc = g_ktp + (size_t)(((half * 4 + nb) * 4 + kc)) * 8192;
    const unsigned qb = smem_s + (unsigned)(s & 1) * 65536u;
    const unsigned kb = qb + 32768u;
#pragma unroll
    for (int n = 0; n < 8; n++) {
        const int fidx = n * 256 + tid;
        CPA16(qb + fidx * 16, (const void*)(qsrc + fidx * 4));
    }
#pragma unroll
    for (int n = 0; n < 8; n++) {
        const int fidx = n * 256 + tid;
        CPA16(kb + fidx * 16, (const void*)(ksrc + fidx * 4));
    }
    CPCOMMIT();
}

__global__ __launch_bounds__(256, 1)
void pkr_gemm(void)
{
    extern __shared__ float smem[];
    const int tid = threadIdx.x;
    const int ty = tid >> 4;     // rows ty*8..+7
    const int tx = tid & 15;     // col groups
    const unsigned smem_s = (unsigned)__cvta_generic_to_shared(smem);
    const int rowBase = blockIdx.x * 128;

    gemm_issue(0, blockIdx.x, smem_s, tid);
    gemm_issue(1, blockIdx.x, smem_s, tid);

    unsigned long long acc[8][8];

#pragma unroll 1
    for (int s = 0; s < 32; ++s) {
        const int half = s >> 4, nb = (s >> 2) & 3, kc = s & 3;

        if (s < 31) { CPWAIT(1); } else { CPWAIT(0); }
        __syncthreads();

        if (kc == 0) {
#pragma unroll
            for (int p = 0; p < 8; p++)
#pragma unroll
                for (int c = 0; c < 8; c++) acc[p][c] = 0ull;
        }

        const float* qp0 = smem + (s & 1) * 16384 + ty * 16;
        const float* kp0 = smem + (s & 1) * 16384 + 8192 + tx * 4;

#pragma unroll 4
        for (int kq = 0; kq < 32; kq++) {
            unsigned long long qd[8];
#pragma unroll
            for (int ci = 0; ci < 4; ci++) {
                uint4 qv = *(const uint4*)(qp0 + kq * 256 + ci * 4);
                qd[2 * ci]     = *(unsigned long long*)&qv.x;
                qd[2 * ci + 1] = *(unsigned long long*)&qv.z;
            }
#pragma unroll
            for (int cl = 0; cl < 4; cl++) {
                uint4 kv = *(const uint4*)(kp0 + kq * 256 + cl * 64);
                unsigned long long k0 = *(unsigned long long*)&kv.x;
                unsigned long long k1 = *(unsigned long long*)&kv.z;
#pragma unroll
                for (int p = 0; p < 8; p++) {
                    FMA2(acc[p][2 * cl],     qd[p], k0);
                    FMA2(acc[p][2 * cl + 1], qd[p], k1);
                }
            }
        }
        __syncthreads();

        if (s < 30) gemm_issue(s + 2, blockIdx.x, smem_s, tid);

        if (kc == 3) {
            const int col0 = half * 1024 + nb * 256;
#pragma unroll
            for (int p = 0; p < 8; p++) {
                const int row = rowBase + ty * 8 + p;
#pragma unroll
                for (int cl = 0; cl < 4; cl++) {
                    float2 f0 = *(float2*)&acc[p][2 * cl];
                    float2 f1 = *(float2*)&acc[p][2 * cl + 1];
                    *(float4*)(g_scores + (size_t)row * 2048 + col0
                               + (4 * tx + cl) * 4)
                        = make_float4(f0.x, f0.y, f1.x, f1.y);
                }
            }
        }
    }
}

// ---------------------------------------------------------------------------
// K4: selection — scan-compaction + bitonic-64 fast path, ballot fallback.
// 2 warps/row (one per half), then 50-candidate joint top-16.
// ---------------------------------------------------------------------------
__global__ __launch_bounds__(256)
void pkr_select(float* __restrict__ out, int Rtot)
{
    __shared__ unsigned long long smQ[8][64];
    __shared__ unsigned long long smK[4][2][16];

    const int lane = threadIdx.x & 31;
    const int warp = threadIdx.x >> 5;
    const int r4   = warp >> 1;
    const int half = warp & 1;
    const int row  = blockIdx.x * 4 + r4;

    const float4* bp = (const float4*)(g_scores + (size_t)row * 2048 + half * 1024);
    float4 sv[8];
#pragma unroll
    for (int q2 = 0; q2 < 8; q2++) sv[q2] = bp[q2 * 32 + lane];

    float vmax = -3.4e38f;
#pragma unroll
    for (int q2 = 0; q2 < 8; q2++)
        vmax = fmaxf(vmax, fmaxf(fmaxf(sv[q2].x, sv[q2].y), fmaxf(sv[q2].z, sv[q2].w)));
    float pm = fmaxf(vmax, __shfl_xor_sync(FULLMASK, vmax, 1));
#pragma unroll
    for (int off = 2; off <= 16; off <<= 1)
        pm = fminf(pm, __shfl_xor_sync(FULLMASK, pm, off));
    const float T0f = pm;

    int cnt = 0;
#pragma unroll
    for (int q2 = 0; q2 < 8; q2++) {
        const float* vv = (const float*)&sv[q2];
#pragma unroll
        for (int t = 0; t < 4; t++) cnt += (vv[t] >= T0f);
    }
    int inc = cnt;
#pragma unroll
    for (int off = 1; off <= 16; off <<= 1) {
        int n = __shfl_up_sync(FULLMASK, inc, off);
        if (lane >= off) inc += n;
    }
    const int total = __shfl_sync(FULLMASK, inc, 31);
    int myoff = inc - cnt;

    unsigned long long rk = 0ull;
    const int lbase = 1023 - lane * 4;

    if (total <= 64) {
        smQ[warp][lane] = 0ull;
        smQ[warp][lane + 32] = 0ull;
        __syncwarp();
#pragma unroll
        for (int q2 = 0; q2 < 8; q2++) {
            const float* vv = (const float*)&sv[q2];
#pragma unroll
            for (int t = 0; t < 4; t++) {
                const float v = vv[t];
                if (v >= T0f) {
                    smQ[warp][myoff++] =
                        ((unsigned long long)fmono(v) << 32)
                        | (unsigned)(lbase - q2 * 128 - t);
                }
            }
        }
        __syncwarp();
        unsigned long long a = smQ[warp][lane];
        unsigned long long b = smQ[warp][lane + 32];
#pragma unroll
        for (int k = 2; k <= 64; k <<= 1) {
#pragma unroll
            for (int j = 32; j >= 1; j >>= 1) {
                if (j >= k) continue;
                if (j == 32) {
                    unsigned long long mx = a > b ? a : b;
                    unsigned long long mn = a > b ? b : a;
                    a = mx; b = mn;
                } else {
                    const bool upa = ((lane & k) != 0);
                    const bool upb = (((lane + 32) & k) != 0);
                    const bool sel = ((lane & j) != 0);
                    unsigned long long oa = __shfl_xor_sync(FULLMASK, a, j);
                    unsigned long long ob = __shfl_xor_sync(FULLMASK, b, j);
                    a = (sel == upa) ? (a > oa ? a : oa) : (a < oa ? a : oa);
                    b = (sel == upb) ? (b > ob ? b : ob) : (b < ob ? b : ob);
                }
            }
        }
        rk = a;
    } else {
        float Tf = T0f;
#pragma unroll
        for (int q2 = 0; q2 < 8; q2++) {
            const float* vv = (const float*)&sv[q2];
#pragma unroll
            for (int t = 0; t < 4; t++) {
                const float v = vv[t];
                const bool p = (v >= Tf);
                unsigned long long K = ((unsigned long long)fmono(v) << 32)
                                     | (unsigned)(lbase - q2 * 128 - t);
                unsigned bal = __ballot_sync(FULLMASK, p);
                while (bal) {
                    const int src = __ffs(bal) - 1;
                    bal &= bal - 1;
                    const unsigned long long Kc = __shfl_sync(FULLMASK, K, src);
                    const unsigned mg = __ballot_sync(FULLMASK, (lane < 16) && (Kc > rk));
                    if (mg) {
                        const int pos = __ffs(mg) - 1;
                        const unsigned long long up = __shfl_up_sync(FULLMASK, rk, 1);
                        if (lane >= pos && lane < 16) rk = (lane == pos) ? Kc : up;
                    }
                    const unsigned long long T16 = __shfl_sync(FULLMASK, rk, 15);
                    Tf = fmaxf(T0f, funmono((unsigned)(T16 >> 32)));
                }
            }
        }
    }
    if (lane < 16) smK[r4][half][lane] = rk;
    __syncthreads();

    if (warp < 4) {
        const int jr = warp;
        const unsigned long long k1 = smK[jr][0][lane & 15];
        const unsigned long long k2 = smK[jr][1][lane & 15];
        const float s1c = funmono((unsigned)(k1 >> 32));
        const float s2c = funmono((unsigned)(k2 >> 32));
        const int e1v = 1023 - (int)(unsigned)k1;
        const int e2v = 1023 - (int)(unsigned)k2;
        const int jrow = blockIdx.x * 4 + jr;

        const int i0 = c_CI[lane], j0 = c_CJ[lane];
        const int cid1 = lane + 32;
        const bool v1 = (cid1 < 50);
        const int i1 = c_CI[v1 ? cid1 : 0], j1 = c_CJ[v1 ? cid1 : 0];

        const float a0 = __shfl_sync(FULLMASK, s1c, i0);
        const float b0 = __shfl_sync(FULLMASK, s2c, j0);
        const float a1 = __shfl_sync(FULLMASK, s1c, i1);
        const float b1 = __shfl_sync(FULLMASK, s2c, j1);

        unsigned long long K0 =
            ((unsigned long long)fmono(a0 + b0) << 32) | (unsigned)(4095 - (i0 * 64 + j0));
        unsigned long long K1 = v1
            ? (((unsigned long long)fmono(a1 + b1) << 32) | (unsigned)(4095 - (i1 * 64 + j1)))
            : 0ull;

        unsigned long long last = ~0ull;
        unsigned long long resKey = 0ull;
#pragma unroll
        for (int r = 0; r < 16; r++) {
            unsigned long long m = (K0 < last) ? K0 : 0ull;
            if (K1 < last && K1 > m) m = K1;
#pragma unroll
            for (int off = 16; off >= 1; off >>= 1) {
                const unsigned long long o = __shfl_xor_sync(FULLMASK, m, off);
                if (o > m) m = o;
            }
            last = m;
            if (lane == r) resKey = m;
        }

        const int flat = 4095 - (int)((unsigned)resKey & 0xFFFu);
        const int ri = (flat >> 6) & 31;
        const int rj = flat & 31;
        const int er = __shfl_sync(FULLMASK, e1v, ri);
        const int ec = __shfl_sync(FULLMASK, e2v, rj);

        if (lane < 16) {
            out[(size_t)jrow * 16 + lane] = (float)(er * 1024 + ec);
            out[(size_t)Rtot * 16 + (size_t)jrow * 16 + lane] =
                funmono((unsigned)(resKey >> 32));
        }
    }
}

// ---------------------------------------------------------------------------
extern "C" void kernel_launch(void* const* d_in, const int* in_sizes, int n_in,
                              void* d_out, int out_size)
{
    const float* q   = (const float*)d_in[0];
    const float* ck  = (const float*)d_in[1];
    const float* cpk = (const float*)d_in[2];
    const float* gm  = (const float*)d_in[3];
    const float* bt  = (const float*)d_in[4];

    const int R = in_sizes[0] / 256;  // 65536

    cudaFuncSetAttribute(pkr_gemm, cudaFuncAttributeMaxDynamicSharedMemorySize, 131072);

    pkr_ln<<<R / 32, 256>>>(q, gm, bt);
    pkr_kprep<<<1024, 256>>>(ck, cpk);
    pkr_gemm<<<R / 128, 256, 131072>>>();
    pkr_select<<<R / 4, 256>>>((float*)d_out, R);
}